// round 13
// baseline (speedup 1.0000x reference)
#include <cuda_runtime.h>
#include <cuda_bf16.h>
#include <stdint.h>

// ---------------- problem constants ----------------
#define I_N 1024
#define O_N 36
#define C_N 1024
#define W_N 60
#define D_N 64
#define MARGIN 0.2f

#define IMG_PER_CTA 7
#define NCTA 147            // ceil(1024/7)
#define THREADS 512         // 16 warps; warp w owns m16-tile w (256 rows total)
#define CAP_BATCH 8         // captions per B buffer = 4 packed pairs
#define NBATCH (C_N / CAP_BATCH)

// ---------------- smem layout (bytes from 1024-aligned base) ----------------
#define OFF_A    0          // 256 rows x 128B (bf16)            = 32768
#define OFF_B    32768      // 2 bufs x 64KB (4 pairs x 16KB)    = 131072
#define OFF_RMAX 163840     // 2 bufs x 8 x 256 floats           = 16384
#define OFF_INV  180224     // 7 floats
#define SMEM_BYTES (180256 + 1024)

// ---------------- device globals ----------------
__device__ __nv_bfloat16 gA [(size_t)I_N * O_N * D_N];
// Pair-packed B: pair p holds caption 2p's words then caption 2p+1's words,
// contiguous; tail cols duplicate cap 2p+1's last word. [pair][col<128][d]
__device__ __nv_bfloat16 gB [(size_t)(C_N / 2) * 128 * D_N];
__device__ float g_scores[(size_t)I_N * C_N];
__device__ float g_diag[I_N];
__device__ float g_partial[I_N];

// ---------------- helpers ----------------
__device__ __forceinline__ uint32_t smem_u32(const void* p) {
    uint32_t a;
    asm("{ .reg .u64 t; cvta.to.shared.u64 t, %1; cvt.u32.u64 %0, t; }" : "=r"(a) : "l"(p));
    return a;
}
#define SW128(off) ((off) ^ (((off) >> 3) & 0x70))

__device__ __forceinline__ void ldsm4(uint32_t* r, uint32_t addr) {
    asm volatile("ldmatrix.sync.aligned.m8n8.x4.shared.b16 {%0,%1,%2,%3}, [%4];"
                 : "=r"(r[0]), "=r"(r[1]), "=r"(r[2]), "=r"(r[3]) : "r"(addr));
}
__device__ __forceinline__ void mma16816(float* d, const uint32_t* a, const uint32_t* b) {
    asm volatile(
        "mma.sync.aligned.m16n8k16.row.col.f32.bf16.bf16.f32 "
        "{%0,%1,%2,%3}, {%4,%5,%6,%7}, {%8,%9}, {%0,%1,%2,%3};"
        : "+f"(d[0]), "+f"(d[1]), "+f"(d[2]), "+f"(d[3])
        : "r"(a[0]), "r"(a[1]), "r"(a[2]), "r"(a[3]), "r"(b[0]), "r"(b[1]));
}
#define CP16(dst, src) \
    asm volatile("cp.async.cg.shared.global [%0], [%1], 16;" :: "r"(dst), "l"(src))
#define CP_COMMIT()  asm volatile("cp.async.commit_group;" ::: "memory")
#define CP_WAIT(n)   asm volatile("cp.async.wait_group %0;" :: "n"(n) : "memory")

// Route one tile's 4 accumulator values into mxA/mxB.
// Warp-uniform branch on tile index vs boundary tile tb; only the single
// boundary tile per pair pays per-column predication.
#define ROUTE_TILE(t, a) do { \
    if ((t) < tb) { \
        mxA[0] = fmaxf(mxA[0], fmaxf((a)[0], (a)[1])); \
        mxA[1] = fmaxf(mxA[1], fmaxf((a)[2], (a)[3])); \
    } else if ((t) > tb || rb == 0) { \
        mxB[0] = fmaxf(mxB[0], fmaxf((a)[0], (a)[1])); \
        mxB[1] = fmaxf(mxB[1], fmaxf((a)[2], (a)[3])); \
    } else { \
        if (colq < rb) { mxA[0] = fmaxf(mxA[0], (a)[0]); mxA[1] = fmaxf(mxA[1], (a)[2]); } \
        else           { mxB[0] = fmaxf(mxB[0], (a)[0]); mxB[1] = fmaxf(mxB[1], (a)[2]); } \
        if (colq + 1 < rb) { mxA[0] = fmaxf(mxA[0], (a)[1]); mxA[1] = fmaxf(mxA[1], (a)[3]); } \
        else               { mxB[0] = fmaxf(mxB[0], (a)[1]); mxB[1] = fmaxf(mxB[1], (a)[3]); } \
    } \
} while (0)

// ---------------- fused precompute: A convert + B pack/convert ----------------
#define NA (I_N * O_N * D_N)
#define NB ((C_N / 2) * 128 * D_N)
extern "C" __global__ void conv_kernel(const float* __restrict__ im,
                                       const float* __restrict__ s,
                                       const int* __restrict__ s_l)
{
    size_t idx = (size_t)blockIdx.x * blockDim.x + threadIdx.x;
    if (idx < (size_t)NA) {
        gA[idx] = __float2bfloat16(im[idx]);
    } else if (idx < (size_t)NA + NB) {
        size_t b = idx - NA;
        int d = (int)(b & 63);
        int q = ((int)(b >> 6)) & 127;     // packed column within pair
        int p = (int)(b >> 13);            // pair index
        int l0 = s_l[2 * p];
        int l1 = s_l[2 * p + 1];
        int c, w;
        if (q < l0)           { c = 2 * p;     w = q; }
        else if (q < l0 + l1) { c = 2 * p + 1; w = q - l0; }
        else                  { c = 2 * p + 1; w = l1 - 1; }   // duplicate pad
        gB[b] = __float2bfloat16(s[((size_t)c * W_N + w) * D_N + d]);
    }
}

// ---------------- main xattn-scores kernel ----------------
extern "C" __global__ void __launch_bounds__(THREADS, 1)
xattn_kernel(const int* __restrict__ im_l, const int* __restrict__ s_l)
{
    extern __shared__ char smraw[];
    const uint32_t raw_u = smem_u32(smraw);
    const uint32_t abase = (raw_u + 1023u) & ~1023u;
    char* base = smraw + (abase - raw_u);

    const int tid  = threadIdx.x;
    const int wid  = tid >> 5;          // 0..15, owns m16-tile wid
    const int lane = tid & 31;
    const int img0 = blockIdx.x * IMG_PER_CTA;
    const int n_img = (I_N - img0 < IMG_PER_CTA) ? (I_N - img0) : IMG_PER_CTA;

    float* rmaxb = (float*)(base + OFF_RMAX);  // [2][8][256]
    float* inv   = (float*)(base + OFF_INV);
    if (tid < n_img)
        inv[tid] = 1.0f / ((float)im_l[img0 + tid] + 1e-6f);

    // ---- stage A into swizzled smem; zero-pad rows >= n_img*36 ----
    {
        const int vchunks = n_img * O_N * 8;
        const uint4* ga = (const uint4*)(gA + (size_t)img0 * O_N * D_N);
        const uint4 z = make_uint4(0, 0, 0, 0);
        #pragma unroll
        for (int t = tid; t < 2048; t += THREADS) {
            uint32_t off = SW128((uint32_t)(t * 16));
            *(uint4*)(base + OFF_A + off) = (t < vchunks) ? ga[t] : z;
        }
    }

    // ---- prefetch B batch 0 (pairs 0..3): 64 KB ----
    {
        const char* sh = (const char*)(gB);
        uint32_t dst = abase + OFF_B;
        #pragma unroll
        for (int t = tid; t < 4096; t += THREADS) {
            uint32_t off = SW128((uint32_t)(t * 16));
            CP16(dst + off, sh + t * 16);
        }
    }
    CP_COMMIT();

    // ---- ldmatrix addressing invariants ----
    const uint32_t xr    = (uint32_t)((lane & 7) << 4);
    const uint32_t aColB = (uint32_t)((lane >> 4) << 4);
    const uint32_t aRow  = (uint32_t)(wid * 16 + (lane & 15));
    const uint32_t bRowOff = (uint32_t)((lane & 7) * 128);
    const uint32_t bMat    = (uint32_t)((lane >> 3) << 4);
    const int colq = (lane & 3) << 1;   // thread's even col within an n8 tile

    // epilogue mapping: quad q (0..55) -> (image q>>3, caption q&7)
    const int quad = tid >> 2;
    const int ql   = tid & 3;
    const int eimg = quad >> 3;
    const int ecap = quad & 7;
    const bool edo = (quad < 56) && (eimg < n_img);

    __syncthreads();   // A staged (needed before ldsm of A)

    // ---- A fragments resident in registers (one m-tile per warp) ----
    uint32_t af[4][4];
    #pragma unroll
    for (int k = 0; k < 4; ++k)
        ldsm4(af[k], abase + OFF_A + aRow * 128 + ((aColB + (uint32_t)(k * 32)) ^ xr));

    for (int cc = 0; cc < NBATCH; ++cc) {
        // prefetch next batch (64 KB)
        if (cc + 1 < NBATCH) {
            const char* sh = (const char*)(gB + (size_t)(cc + 1) * 32768);
            uint32_t dst = abase + OFF_B + (uint32_t)((cc + 1) & 1) * 65536;
            #pragma unroll
            for (int t = tid; t < 4096; t += THREADS) {
                uint32_t off = SW128((uint32_t)(t * 16));
                CP16(dst + off, sh + t * 16);
            }
            CP_COMMIT();
            CP_WAIT(1);
        } else {
            CP_WAIT(0);
        }
        // ONE barrier per batch: orders (a) B(cc) visibility, (b) rmax(cc-1)
        // completeness, (c) WAR on rmax(cc) buffer.
        __syncthreads();

        // ---- deferred score epilogue for batch cc-1 (reads buf (cc-1)&1) ----
        if (cc > 0 && edo) {
            const float* rj = rmaxb + (uint32_t)((cc - 1) & 1) * 2048
                             + ecap * 256 + eimg * O_N;
            float v = 0.0f;
            #pragma unroll
            for (int i = 0; i < 9; ++i)
                v += rj[ql + 4 * i];
            v += __shfl_xor_sync(0xFFFFFFFFu, v, 1);
            v += __shfl_xor_sync(0xFFFFFFFFu, v, 2);
            if (ql == 0) {
                const int gc = CAP_BATCH * (cc - 1) + ecap;
                const int gr = img0 + eimg;
                float sc = v * inv[eimg];
                g_scores[(size_t)gr * C_N + gc] = sc;
                if (gr == gc) g_diag[gc] = sc;   // fused diag extraction
            }
        }

        float* rmax = rmaxb + (uint32_t)(cc & 1) * 2048;   // write buf cc&1

        #pragma unroll
        for (int pp = 0; pp < 4; ++pp) {
            const int l0 = __ldg(s_l + CAP_BATCH * cc + 2 * pp);
            const int l1 = __ldg(s_l + CAP_BATCH * cc + 2 * pp + 1);
            const int Tp = (l0 + l1 + 7) >> 3;   // packed tiles for this pair
            const int tb = l0 >> 3;              // boundary tile index
            const int rb = l0 & 7;               // cap0 cols within boundary tile
            const uint32_t bh_base = abase + OFF_B + (uint32_t)((cc & 1) << 16)
                                    + (uint32_t)(pp << 14);

            float mxA[2] = { -1e30f, -1e30f };
            float mxB[2] = { -1e30f, -1e30f };

            #pragma unroll
            for (int tp = 0; tp < 8; ++tp) {
                const int t0 = 2 * tp;
                if (t0 < Tp) {
                    const bool has2 = (t0 + 1) < Tp;
                    uint32_t bf0[2][4], bf1[2][4];
                    #pragma unroll
                    for (int kp = 0; kp < 2; ++kp)
                        ldsm4(bf0[kp], bh_base + (uint32_t)(t0 * 1024) + bRowOff
                                      + (((uint32_t)(kp * 64) + bMat) ^ xr));
                    if (has2) {
                        #pragma unroll
                        for (int kp = 0; kp < 2; ++kp)
                            ldsm4(bf1[kp], bh_base + (uint32_t)((t0 + 1) * 1024) + bRowOff
                                          + (((uint32_t)(kp * 64) + bMat) ^ xr));
                    }

                    float acc[2][4];
                    #pragma unroll
                    for (int t2 = 0; t2 < 2; ++t2)
                        #pragma unroll
                        for (int q = 0; q < 4; ++q) acc[t2][q] = 0.0f;

                    #pragma unroll
                    for (int k = 0; k < 4; ++k) {
                        mma16816(acc[0], af[k], &bf0[k >> 1][(k & 1) * 2]);
                        if (has2)
                            mma16816(acc[1], af[k], &bf1[k >> 1][(k & 1) * 2]);
                    }

                    ROUTE_TILE(t0, acc[0]);
                    if (has2) ROUTE_TILE(t0 + 1, acc[1]);
                }
            }

            // quad reduce (lanes sharing the same rows); -1e30 from threads
            // whose columns never hit a caption is dominated by real values
            #pragma unroll
            for (int q = 0; q < 2; ++q) {
                mxA[q] = fmaxf(mxA[q], __shfl_xor_sync(0xFFFFFFFFu, mxA[q], 1));
                mxA[q] = fmaxf(mxA[q], __shfl_xor_sync(0xFFFFFFFFu, mxA[q], 2));
                mxB[q] = fmaxf(mxB[q], __shfl_xor_sync(0xFFFFFFFFu, mxB[q], 1));
                mxB[q] = fmaxf(mxB[q], __shfl_xor_sync(0xFFFFFFFFu, mxB[q], 2));
            }
            if ((lane & 3) == 0) {
                const int row0 = wid * 16 + (lane >> 2);
                float* rA = rmax + (2 * pp) * 256;
                float* rB = rmax + (2 * pp + 1) * 256;
                rA[row0]     = mxA[0];
                rA[row0 + 8] = mxA[1];
                rB[row0]     = mxB[0];
                rB[row0 + 8] = mxB[1];
            }
        }
    }

    // ---- final batch's epilogue ----
    __syncthreads();
    if (edo) {
        const float* rj = rmaxb + (uint32_t)((NBATCH - 1) & 1) * 2048
                         + ecap * 256 + eimg * O_N;
        float v = 0.0f;
        #pragma unroll
        for (int i = 0; i < 9; ++i)
            v += rj[ql + 4 * i];
        v += __shfl_xor_sync(0xFFFFFFFFu, v, 1);
        v += __shfl_xor_sync(0xFFFFFFFFu, v, 2);
        if (ql == 0) {
            const int gc = CAP_BATCH * (NBATCH - 1) + ecap;
            const int gr = img0 + eimg;
            float sc = v * inv[eimg];
            g_scores[(size_t)gr * C_N + gc] = sc;
            if (gr == gc) g_diag[gc] = sc;
        }
    }
}

// ---------------- loss epilogue ----------------
extern "C" __global__ void row_kernel()
{
    const int b = blockIdx.x;
    const int tid = threadIdx.x;
    const float di = g_diag[b];
    float local = 0.0f;
    for (int c = tid; c < C_N; c += blockDim.x) {
        if (c == b) continue;
        float sc = g_scores[(size_t)b * C_N + c];
        local += fmaxf(0.0f, MARGIN + sc - di)
               + fmaxf(0.0f, MARGIN + sc - g_diag[c]);
    }
    __shared__ float buf[128];
    buf[tid] = local;
    __syncthreads();
    for (int s = 64; s > 0; s >>= 1) {
        if (tid < s) buf[tid] += buf[tid + s];
        __syncthreads();
    }
    if (tid == 0) g_partial[b] = buf[0];
}

extern "C" __global__ void final_kernel(float* out)
{
    const int tid = threadIdx.x;
    float local = 0.0f;
    for (int i = tid; i < I_N; i += 256) local += g_partial[i];
    __shared__ float buf[256];
    buf[tid] = local;
    __syncthreads();
    for (int s = 128; s > 0; s >>= 1) {
        if (tid < s) buf[tid] += buf[tid + s];
        __syncthreads();
    }
    if (tid == 0) out[0] = buf[0] * (1.0f / ((float)I_N * (float)C_N));
}

// ---------------- launch ----------------
extern "C" void kernel_launch(void* const* d_in, const int* in_sizes, int n_in,
                              void* d_out, int out_size)
{
    const float* im   = (const float*)d_in[0];
    const float* s    = (const float*)d_in[1];
    const int*   im_l = (const int*)d_in[2];
    const int*   s_l  = (const int*)d_in[3];

    cudaFuncSetAttribute(xattn_kernel,
                         cudaFuncAttributeMaxDynamicSharedMemorySize, SMEM_BYTES);

    conv_kernel<<<(NA + NB + 255) / 256, 256>>>(im, s, s_l);
    xattn_kernel<<<NCTA, THREADS, SMEM_BYTES>>>(im_l, s_l);
    row_kernel<<<I_N, 128>>>();
    final_kernel<<<1, 256>>>((float*)d_out);
}

// round 14
// speedup vs baseline: 1.1678x; 1.1678x over previous
#include <cuda_runtime.h>
#include <cuda_bf16.h>
#include <stdint.h>

// ---------------- problem constants ----------------
#define I_N 1024
#define O_N 36
#define C_N 1024
#define W_N 60
#define D_N 64
#define MARGIN 0.2f

#define IMG_PER_CTA 7
#define NCTA 147            // ceil(1024/7)
#define THREADS 512         // 16 warps; warp w owns m16-tile w (256 rows total)
#define CAP_BATCH 8         // captions per B buffer (8KB each, bf16)
#define NBATCH (C_N / CAP_BATCH)

// ---------------- smem layout (bytes from 1024-aligned base) ----------------
#define OFF_A    0          // 256 rows x 128B (bf16)            = 32768
#define OFF_B    32768      // 2 bufs x 64KB (8 captions each)   = 131072
#define OFF_RMAX 163840     // 2 bufs x 8 x 256 floats           = 16384
#define OFF_INV  180224     // 7 floats
#define SMEM_BYTES (180256 + 1024)

// ---------------- device globals ----------------
__device__ __nv_bfloat16 gA [(size_t)I_N * O_N * D_N];
__device__ __nv_bfloat16 gBh[(size_t)C_N * 64 * D_N];   // words padded to 64 w/ duplicate of last valid word
__device__ float g_scores[(size_t)I_N * C_N];
__device__ float g_diag[I_N];
__device__ float g_partial[I_N];

// ---------------- helpers ----------------
__device__ __forceinline__ uint32_t smem_u32(const void* p) {
    uint32_t a;
    asm("{ .reg .u64 t; cvta.to.shared.u64 t, %1; cvt.u32.u64 %0, t; }" : "=r"(a) : "l"(p));
    return a;
}
#define SW128(off) ((off) ^ (((off) >> 3) & 0x70))

__device__ __forceinline__ void ldsm4(uint32_t* r, uint32_t addr) {
    asm volatile("ldmatrix.sync.aligned.m8n8.x4.shared.b16 {%0,%1,%2,%3}, [%4];"
                 : "=r"(r[0]), "=r"(r[1]), "=r"(r[2]), "=r"(r[3]) : "r"(addr));
}
__device__ __forceinline__ void mma16816(float* d, const uint32_t* a, const uint32_t* b) {
    asm volatile(
        "mma.sync.aligned.m16n8k16.row.col.f32.bf16.bf16.f32 "
        "{%0,%1,%2,%3}, {%4,%5,%6,%7}, {%8,%9}, {%0,%1,%2,%3};"
        : "+f"(d[0]), "+f"(d[1]), "+f"(d[2]), "+f"(d[3])
        : "r"(a[0]), "r"(a[1]), "r"(a[2]), "r"(a[3]), "r"(b[0]), "r"(b[1]));
}
#define CP16(dst, src) \
    asm volatile("cp.async.cg.shared.global [%0], [%1], 16;" :: "r"(dst), "l"(src))
#define CP_COMMIT()  asm volatile("cp.async.commit_group;" ::: "memory")
#define CP_WAIT(n)   asm volatile("cp.async.wait_group %0;" :: "n"(n) : "memory")

// ---------------- fused precompute: A convert + B convert/pad ----------------
// elems [0, NA) -> gA ; elems [NA, NA+NB) -> gBh
#define NA (I_N * O_N * D_N)
#define NB (C_N * 64 * D_N)
extern "C" __global__ void conv_kernel(const float* __restrict__ im,
                                       const float* __restrict__ s,
                                       const int* __restrict__ s_l)
{
    size_t idx = (size_t)blockIdx.x * blockDim.x + threadIdx.x;
    if (idx < (size_t)NA) {
        gA[idx] = __float2bfloat16(im[idx]);
    } else if (idx < (size_t)NA + NB) {
        size_t b = idx - NA;
        int d = (int)(b & 63);
        int w = ((int)(b >> 6)) & 63;
        int c = (int)(b >> 12);
        int clen = s_l[c];
        // Pad words [clen, 64) with a COPY of word clen-1: max over any computed
        // superset of columns equals the true max -> no masking downstream.
        int ws = (w < clen) ? w : (clen - 1);
        gBh[b] = __float2bfloat16(s[((size_t)c * W_N + ws) * D_N + d]);
    }
}

// ---------------- main xattn-scores kernel ----------------
extern "C" __global__ void __launch_bounds__(THREADS, 1)
xattn_kernel(const int* __restrict__ im_l, const int* __restrict__ s_l)
{
    extern __shared__ char smraw[];
    const uint32_t raw_u = smem_u32(smraw);
    const uint32_t abase = (raw_u + 1023u) & ~1023u;
    char* base = smraw + (abase - raw_u);

    const int tid  = threadIdx.x;
    const int wid  = tid >> 5;          // 0..15, owns m16-tile wid
    const int lane = tid & 31;
    const int img0 = blockIdx.x * IMG_PER_CTA;
    const int n_img = (I_N - img0 < IMG_PER_CTA) ? (I_N - img0) : IMG_PER_CTA;

    float* rmaxb = (float*)(base + OFF_RMAX);  // [2][8][256]
    float* inv   = (float*)(base + OFF_INV);
    if (tid < n_img)
        inv[tid] = 1.0f / ((float)im_l[img0 + tid] + 1e-6f);

    // ---- stage A into swizzled smem; zero-pad rows >= n_img*36 ----
    {
        const int vchunks = n_img * O_N * 8;
        const uint4* ga = (const uint4*)(gA + (size_t)img0 * O_N * D_N);
        const uint4 z = make_uint4(0, 0, 0, 0);
        #pragma unroll
        for (int t = tid; t < 2048; t += THREADS) {
            uint32_t off = SW128((uint32_t)(t * 16));
            *(uint4*)(base + OFF_A + off) = (t < vchunks) ? ga[t] : z;
        }
    }

    // ---- prefetch B batch 0 (captions 0..7): 64 KB ----
    {
        const char* sh = (const char*)(gBh);
        uint32_t dst = abase + OFF_B;
        #pragma unroll
        for (int t = tid; t < 4096; t += THREADS) {
            uint32_t off = SW128((uint32_t)(t * 16));
            CP16(dst + off, sh + t * 16);
        }
    }
    CP_COMMIT();

    // ---- ldmatrix addressing invariants ----
    const uint32_t xr    = (uint32_t)((lane & 7) << 4);
    const uint32_t aColB = (uint32_t)((lane >> 4) << 4);
    const uint32_t aRow  = (uint32_t)(wid * 16 + (lane & 15));
    // B ldsm4: lane L -> row (L&7), matrix (L>>3); one x4 covers 2 k-steps.
    const uint32_t bRowOff = (uint32_t)((lane & 7) * 128);
    const uint32_t bMat    = (uint32_t)((lane >> 3) << 4);

    // epilogue mapping: quad q (0..55) -> (image q>>3, caption q&7)
    const int quad = tid >> 2;
    const int ql   = tid & 3;
    const int eimg = quad >> 3;
    const int ecap = quad & 7;
    const bool edo = (quad < 56) && (eimg < n_img);

    __syncthreads();   // A staged (needed before ldsm of A)

    // ---- A fragments resident in registers (one m-tile per warp) ----
    uint32_t af[4][4];
    #pragma unroll
    for (int k = 0; k < 4; ++k)
        ldsm4(af[k], abase + OFF_A + aRow * 128 + ((aColB + (uint32_t)(k * 32)) ^ xr));

    for (int cc = 0; cc < NBATCH; ++cc) {
        // prefetch next batch (64 KB)
        if (cc + 1 < NBATCH) {
            const char* sh = (const char*)(gBh + (size_t)(cc + 1) * 32768);
            uint32_t dst = abase + OFF_B + (uint32_t)((cc + 1) & 1) * 65536;
            #pragma unroll
            for (int t = tid; t < 4096; t += THREADS) {
                uint32_t off = SW128((uint32_t)(t * 16));
                CP16(dst + off, sh + t * 16);
            }
            CP_COMMIT();
            CP_WAIT(1);
        } else {
            CP_WAIT(0);
        }
        // ONE barrier per batch: orders (a) B(cc) visibility for all warps,
        // (b) completeness of rmax(cc-1) writes, (c) WAR on rmax(cc) buffer.
        __syncthreads();

        // ---- deferred score epilogue for batch cc-1 (reads buf (cc-1)&1) ----
        if (cc > 0 && edo) {
            const float* rj = rmaxb + (uint32_t)((cc - 1) & 1) * 2048
                             + ecap * 256 + eimg * O_N;
            float v = 0.0f;
            #pragma unroll
            for (int i = 0; i < 9; ++i)
                v += rj[ql + 4 * i];
            v += __shfl_xor_sync(0xFFFFFFFFu, v, 1);
            v += __shfl_xor_sync(0xFFFFFFFFu, v, 2);
            if (ql == 0) {
                const int gc = CAP_BATCH * (cc - 1) + ecap;
                const int gr = img0 + eimg;
                float sc = v * inv[eimg];
                g_scores[(size_t)gr * C_N + gc] = sc;
                if (gr == gc) g_diag[gc] = sc;   // fused diag extraction
            }
        }

        float* rmax = rmaxb + (uint32_t)(cc & 1) * 2048;   // write buf cc&1

        #pragma unroll
        for (int j = 0; j < CAP_BATCH; ++j) {
            const int clen = __ldg(&s_l[CAP_BATCH * cc + j]);   // scalar: verified-correct
            const int nlim = (clen + 7) >> 3;      // n8 tiles to compute
            const uint32_t bh_base = abase + OFF_B + (uint32_t)((cc & 1) << 16)
                                    + (uint32_t)(j << 13);

            float mx[2] = { -1e30f, -1e30f };

            #pragma unroll
            for (int p = 0; p < 4; ++p) {
                const int n0 = 2 * p;
                if (n0 < nlim) {
                    const bool has2 = (n0 + 1) < nlim;
                    // bf[kp][0..3]: {r0,r1}=k-step 2kp, {r2,r3}=k-step 2kp+1
                    uint32_t bf0[2][4], bf1[2][4];
                    #pragma unroll
                    for (int kp = 0; kp < 2; ++kp)
                        ldsm4(bf0[kp], bh_base + (uint32_t)(n0 * 1024) + bRowOff
                                      + (((uint32_t)(kp * 64) + bMat) ^ xr));
                    if (has2) {
                        #pragma unroll
                        for (int kp = 0; kp < 2; ++kp)
                            ldsm4(bf1[kp], bh_base + (uint32_t)((n0 + 1) * 1024) + bRowOff
                                          + (((uint32_t)(kp * 64) + bMat) ^ xr));
                    }

                    float acc[2][4];
                    #pragma unroll
                    for (int t2 = 0; t2 < 2; ++t2)
                        #pragma unroll
                        for (int q = 0; q < 4; ++q) acc[t2][q] = 0.0f;

                    #pragma unroll
                    for (int k = 0; k < 4; ++k) {
                        mma16816(acc[0], af[k], &bf0[k >> 1][(k & 1) * 2]);
                        if (has2)
                            mma16816(acc[1], af[k], &bf1[k >> 1][(k & 1) * 2]);
                    }

                    mx[0] = fmaxf(mx[0], fmaxf(acc[0][0], acc[0][1]));
                    mx[1] = fmaxf(mx[1], fmaxf(acc[0][2], acc[0][3]));
                    if (has2) {
                        mx[0] = fmaxf(mx[0], fmaxf(acc[1][0], acc[1][1]));
                        mx[1] = fmaxf(mx[1], fmaxf(acc[1][2], acc[1][3]));
                    }
                }
            }

            // quad reduce (lanes sharing the same rows)
            #pragma unroll
            for (int q = 0; q < 2; ++q) {
                mx[q] = fmaxf(mx[q], __shfl_xor_sync(0xFFFFFFFFu, mx[q], 1));
                mx[q] = fmaxf(mx[q], __shfl_xor_sync(0xFFFFFFFFu, mx[q], 2));
            }
            if ((lane & 3) == 0) {
                float* rj = rmax + j * 256;
                const int row0 = wid * 16 + (lane >> 2);
                rj[row0]     = mx[0];
                rj[row0 + 8] = mx[1];
            }
        }
    }

    // ---- final batch's epilogue ----
    __syncthreads();
    if (edo) {
        const float* rj = rmaxb + (uint32_t)((NBATCH - 1) & 1) * 2048
                         + ecap * 256 + eimg * O_N;
        float v = 0.0f;
        #pragma unroll
        for (int i = 0; i < 9; ++i)
            v += rj[ql + 4 * i];
        v += __shfl_xor_sync(0xFFFFFFFFu, v, 1);
        v += __shfl_xor_sync(0xFFFFFFFFu, v, 2);
        if (ql == 0) {
            const int gc = CAP_BATCH * (NBATCH - 1) + ecap;
            const int gr = img0 + eimg;
            float sc = v * inv[eimg];
            g_scores[(size_t)gr * C_N + gc] = sc;
            if (gr == gc) g_diag[gc] = sc;
        }
    }
}

// ---------------- loss epilogue ----------------
extern "C" __global__ void row_kernel()
{
    const int b = blockIdx.x;
    const int tid = threadIdx.x;
    const float di = g_diag[b];
    float local = 0.0f;
    for (int c = tid; c < C_N; c += blockDim.x) {
        if (c == b) continue;
        float sc = g_scores[(size_t)b * C_N + c];
        local += fmaxf(0.0f, MARGIN + sc - di)
               + fmaxf(0.0f, MARGIN + sc - g_diag[c]);
    }
    __shared__ float buf[128];
    buf[tid] = local;
    __syncthreads();
    for (int s = 64; s > 0; s >>= 1) {
        if (tid < s) buf[tid] += buf[tid + s];
        __syncthreads();
    }
    if (tid == 0) g_partial[b] = buf[0];
}

extern "C" __global__ void final_kernel(float* out)
{
    const int tid = threadIdx.x;
    float local = 0.0f;
    for (int i = tid; i < I_N; i += 256) local += g_partial[i];
    __shared__ float buf[256];
    buf[tid] = local;
    __syncthreads();
    for (int s = 128; s > 0; s >>= 1) {
        if (tid < s) buf[tid] += buf[tid + s];
        __syncthreads();
    }
    if (tid == 0) out[0] = buf[0] * (1.0f / ((float)I_N * (float)C_N));
}

// ---------------- launch ----------------
extern "C" void kernel_launch(void* const* d_in, const int* in_sizes, int n_in,
                              void* d_out, int out_size)
{
    const float* im   = (const float*)d_in[0];
    const float* s    = (const float*)d_in[1];
    const int*   im_l = (const int*)d_in[2];
    const int*   s_l  = (const int*)d_in[3];

    cudaFuncSetAttribute(xattn_kernel,
                         cudaFuncAttributeMaxDynamicSharedMemorySize, SMEM_BYTES);

    conv_kernel<<<(NA + NB + 255) / 256, 256>>>(im, s, s_l);
    xattn_kernel<<<NCTA, THREADS, SMEM_BYTES>>>(im_l, s_l);
    row_kernel<<<I_N, 128>>>();
    final_kernel<<<1, 256>>>((float*)d_out);
}

// round 15
// speedup vs baseline: 1.2030x; 1.0302x over previous
#include <cuda_runtime.h>
#include <cuda_bf16.h>
#include <stdint.h>

// ---------------- problem constants ----------------
#define I_N 1024
#define O_N 36
#define C_N 1024
#define W_N 60
#define D_N 64
#define MARGIN 0.2f

#define IMG_PER_CTA 7
#define NCTA 147            // ceil(1024/7)
#define THREADS 512         // 16 warps; warp w owns m16-tile w (256 rows total)
#define CAP_BATCH 8         // captions per B buffer (8KB each, bf16)
#define NBATCH (C_N / CAP_BATCH)

// ---------------- smem layout (bytes from 1024-aligned base) ----------------
#define OFF_A    0          // 256 rows x 128B (bf16)            = 32768
#define OFF_B    32768      // 2 bufs x 64KB (8 captions each)   = 131072
#define OFF_RMAX 163840     // 2 bufs x 8 x 256 floats           = 16384
#define OFF_INV  180224     // 7 floats
#define SMEM_BYTES (180256 + 1024)

// ---------------- device globals ----------------
__device__ __nv_bfloat16 gA [(size_t)I_N * O_N * D_N];
__device__ __nv_bfloat16 gBh[(size_t)C_N * 64 * D_N];   // words padded to 64 w/ duplicate of last valid word
__device__ float g_scores[(size_t)I_N * C_N];
__device__ float g_diag[I_N];
__device__ float g_partial[I_N];

// ---------------- helpers ----------------
__device__ __forceinline__ uint32_t smem_u32(const void* p) {
    uint32_t a;
    asm("{ .reg .u64 t; cvta.to.shared.u64 t, %1; cvt.u32.u64 %0, t; }" : "=r"(a) : "l"(p));
    return a;
}
#define SW128(off) ((off) ^ (((off) >> 3) & 0x70))

__device__ __forceinline__ void ldsm4(uint32_t* r, uint32_t addr) {
    asm volatile("ldmatrix.sync.aligned.m8n8.x4.shared.b16 {%0,%1,%2,%3}, [%4];"
                 : "=r"(r[0]), "=r"(r[1]), "=r"(r[2]), "=r"(r[3]) : "r"(addr));
}
__device__ __forceinline__ void mma16816(float* d, const uint32_t* a, const uint32_t* b) {
    asm volatile(
        "mma.sync.aligned.m16n8k16.row.col.f32.bf16.bf16.f32 "
        "{%0,%1,%2,%3}, {%4,%5,%6,%7}, {%8,%9}, {%0,%1,%2,%3};"
        : "+f"(d[0]), "+f"(d[1]), "+f"(d[2]), "+f"(d[3])
        : "r"(a[0]), "r"(a[1]), "r"(a[2]), "r"(a[3]), "r"(b[0]), "r"(b[1]));
}
#define CP16(dst, src) \
    asm volatile("cp.async.cg.shared.global [%0], [%1], 16;" :: "r"(dst), "l"(src))
#define CP_COMMIT()  asm volatile("cp.async.commit_group;" ::: "memory")
#define CP_WAIT(n)   asm volatile("cp.async.wait_group %0;" :: "n"(n) : "memory")

// ---------------- vectorized precompute: A + B convert/pad, 4 elems/thread ----
#define NA (I_N * O_N * D_N)
#define NB (C_N * 64 * D_N)
#define NA4 (NA / 4)
#define NB4 (NB / 4)

__device__ __forceinline__ uint2 cvt4(float4 v) {
    __nv_bfloat162 p0 = __floats2bfloat162_rn(v.x, v.y);
    __nv_bfloat162 p1 = __floats2bfloat162_rn(v.z, v.w);
    uint2 o;
    o.x = *reinterpret_cast<const uint32_t*>(&p0);
    o.y = *reinterpret_cast<const uint32_t*>(&p1);
    return o;
}

extern "C" __global__ void conv_kernel(const float* __restrict__ im,
                                       const float* __restrict__ s,
                                       const int* __restrict__ s_l)
{
    int idx = blockIdx.x * blockDim.x + threadIdx.x;
    if (idx < NA4) {
        float4 v = reinterpret_cast<const float4*>(im)[idx];
        reinterpret_cast<uint2*>(gA)[idx] = cvt4(v);
    } else if (idx < NA4 + NB4) {
        int g = idx - NA4;
        int d4 = g & 15;                 // 4-elem group within d (0..15)
        int w  = (g >> 4) & 63;          // padded word column
        int c  = g >> 10;                // caption
        int clen = s_l[c];
        // Pad words [clen, 64) with a COPY of word clen-1: max over any computed
        // superset of columns equals the true max -> no masking downstream.
        int ws = (w < clen) ? w : (clen - 1);
        float4 v = reinterpret_cast<const float4*>(
                       s + ((size_t)c * W_N + ws) * D_N)[d4];
        reinterpret_cast<uint2*>(gBh)[(c << 10) + (w << 4) + d4] = cvt4(v);
    }
}

// ---------------- main xattn-scores kernel ----------------
extern "C" __global__ void __launch_bounds__(THREADS, 1)
xattn_kernel(const int* __restrict__ im_l, const int* __restrict__ s_l)
{
    extern __shared__ char smraw[];
    const uint32_t raw_u = smem_u32(smraw);
    const uint32_t abase = (raw_u + 1023u) & ~1023u;
    char* base = smraw + (abase - raw_u);

    const int tid  = threadIdx.x;
    const int wid  = tid >> 5;          // 0..15, owns m16-tile wid
    const int lane = tid & 31;
    const int img0 = blockIdx.x * IMG_PER_CTA;
    const int n_img = (I_N - img0 < IMG_PER_CTA) ? (I_N - img0) : IMG_PER_CTA;

    float* rmaxb = (float*)(base + OFF_RMAX);  // [2][8][256]
    float* inv   = (float*)(base + OFF_INV);
    if (tid < n_img)
        inv[tid] = 1.0f / ((float)im_l[img0 + tid] + 1e-6f);

    // ---- stage A into swizzled smem; zero-pad rows >= n_img*36 ----
    {
        const int vchunks = n_img * O_N * 8;
        const uint4* ga = (const uint4*)(gA + (size_t)img0 * O_N * D_N);
        const uint4 z = make_uint4(0, 0, 0, 0);
        #pragma unroll
        for (int t = tid; t < 2048; t += THREADS) {
            uint32_t off = SW128((uint32_t)(t * 16));
            *(uint4*)(base + OFF_A + off) = (t < vchunks) ? ga[t] : z;
        }
    }

    // ---- prefetch B batch 0 (captions 0..7): 64 KB ----
    {
        const char* sh = (const char*)(gBh);
        uint32_t dst = abase + OFF_B;
        #pragma unroll
        for (int t = tid; t < 4096; t += THREADS) {
            uint32_t off = SW128((uint32_t)(t * 16));
            CP16(dst + off, sh + t * 16);
        }
    }
    CP_COMMIT();

    // ---- ldmatrix addressing invariants ----
    const uint32_t xr    = (uint32_t)((lane & 7) << 4);
    const uint32_t aColB = (uint32_t)((lane >> 4) << 4);
    const uint32_t aRow  = (uint32_t)(wid * 16 + (lane & 15));
    // B ldsm4: lane L -> row (L&7), matrix (L>>3); one x4 covers 2 k-steps.
    const uint32_t bRowOff = (uint32_t)((lane & 7) * 128);
    const uint32_t bMat    = (uint32_t)((lane >> 3) << 4);

    // epilogue mapping: quad q (0..55) -> (image q>>3, caption q&7)
    const int quad = tid >> 2;
    const int ql   = tid & 3;
    const int eimg = quad >> 3;
    const int ecap = quad & 7;
    const bool edo = (quad < 56) && (eimg < n_img);

    __syncthreads();   // A staged (needed before ldsm of A)

    // ---- A fragments resident in registers (one m-tile per warp) ----
    uint32_t af[4][4];
    #pragma unroll
    for (int k = 0; k < 4; ++k)
        ldsm4(af[k], abase + OFF_A + aRow * 128 + ((aColB + (uint32_t)(k * 32)) ^ xr));

    for (int cc = 0; cc < NBATCH; ++cc) {
        // prefetch next batch (64 KB)
        if (cc + 1 < NBATCH) {
            const char* sh = (const char*)(gBh + (size_t)(cc + 1) * 32768);
            uint32_t dst = abase + OFF_B + (uint32_t)((cc + 1) & 1) * 65536;
            #pragma unroll
            for (int t = tid; t < 4096; t += THREADS) {
                uint32_t off = SW128((uint32_t)(t * 16));
                CP16(dst + off, sh + t * 16);
            }
            CP_COMMIT();
            CP_WAIT(1);
        } else {
            CP_WAIT(0);
        }
        // ONE barrier per batch: orders (a) B(cc) visibility for all warps,
        // (b) completeness of rmax(cc-1) writes, (c) WAR on rmax(cc) buffer.
        __syncthreads();

        // ---- deferred score epilogue for batch cc-1 (reads buf (cc-1)&1) ----
        if (cc > 0 && edo) {
            const float* rj = rmaxb + (uint32_t)((cc - 1) & 1) * 2048
                             + ecap * 256 + eimg * O_N;
            float v = 0.0f;
            #pragma unroll
            for (int i = 0; i < 9; ++i)
                v += rj[ql + 4 * i];
            v += __shfl_xor_sync(0xFFFFFFFFu, v, 1);
            v += __shfl_xor_sync(0xFFFFFFFFu, v, 2);
            if (ql == 0) {
                const int gc = CAP_BATCH * (cc - 1) + ecap;
                const int gr = img0 + eimg;
                float sc = v * inv[eimg];
                g_scores[(size_t)gr * C_N + gc] = sc;
                if (gr == gc) g_diag[gc] = sc;   // fused diag extraction
            }
        }

        // batch caption lengths: 2 vector LDGs (s_l offset is 32B-aligned)
        const int4 cl0 = *(const int4*)(s_l + CAP_BATCH * cc);
        const int4 cl1 = *(const int4*)(s_l + CAP_BATCH * cc + 4);
        const int clens[8] = { cl0.x, cl0.y, cl0.z, cl0.w,
                               cl1.x, cl1.y, cl1.z, cl1.w };

        float* rmax = rmaxb + (uint32_t)(cc & 1) * 2048;   // write buf cc&1

        #pragma unroll
        for (int j = 0; j < CAP_BATCH; ++j) {
            const int nlim = (clens[j] + 7) >> 3;  // n8 tiles to compute
            const uint32_t bh_base = abase + OFF_B + (uint32_t)((cc & 1) << 16)
                                    + (uint32_t)(j << 13);

            float mx[2] = { -1e30f, -1e30f };

            #pragma unroll
            for (int p = 0; p < 4; ++p) {
                const int n0 = 2 * p;
                if (n0 < nlim) {
                    const bool has2 = (n0 + 1) < nlim;
                    // bf[kp][0..3]: {r0,r1}=k-step 2kp, {r2,r3}=k-step 2kp+1
                    uint32_t bf0[2][4], bf1[2][4];
                    #pragma unroll
                    for (int kp = 0; kp < 2; ++kp)
                        ldsm4(bf0[kp], bh_base + (uint32_t)(n0 * 1024) + bRowOff
                                      + (((uint32_t)(kp * 64) + bMat) ^ xr));
                    if (has2) {
                        #pragma unroll
                        for (int kp = 0; kp < 2; ++kp)
                            ldsm4(bf1[kp], bh_base + (uint32_t)((n0 + 1) * 1024) + bRowOff
                                          + (((uint32_t)(kp * 64) + bMat) ^ xr));
                    }

                    float acc[2][4];
                    #pragma unroll
                    for (int t2 = 0; t2 < 2; ++t2)
                        #pragma unroll
                        for (int q = 0; q < 4; ++q) acc[t2][q] = 0.0f;

                    #pragma unroll
                    for (int k = 0; k < 4; ++k) {
                        mma16816(acc[0], af[k], &bf0[k >> 1][(k & 1) * 2]);
                        if (has2)
                            mma16816(acc[1], af[k], &bf1[k >> 1][(k & 1) * 2]);
                    }

                    mx[0] = fmaxf(mx[0], fmaxf(acc[0][0], acc[0][1]));
                    mx[1] = fmaxf(mx[1], fmaxf(acc[0][2], acc[0][3]));
                    if (has2) {
                        mx[0] = fmaxf(mx[0], fmaxf(acc[1][0], acc[1][1]));
                        mx[1] = fmaxf(mx[1], fmaxf(acc[1][2], acc[1][3]));
                    }
                }
            }

            // quad reduce (lanes sharing the same rows)
            #pragma unroll
            for (int q = 0; q < 2; ++q) {
                mx[q] = fmaxf(mx[q], __shfl_xor_sync(0xFFFFFFFFu, mx[q], 1));
                mx[q] = fmaxf(mx[q], __shfl_xor_sync(0xFFFFFFFFu, mx[q], 2));
            }
            if ((lane & 3) == 0) {
                float* rj = rmax + j * 256;
                const int row0 = wid * 16 + (lane >> 2);
                rj[row0]     = mx[0];
                rj[row0 + 8] = mx[1];
            }
        }
    }

    // ---- final batch's epilogue ----
    __syncthreads();
    if (edo) {
        const float* rj = rmaxb + (uint32_t)((NBATCH - 1) & 1) * 2048
                         + ecap * 256 + eimg * O_N;
        float v = 0.0f;
        #pragma unroll
        for (int i = 0; i < 9; ++i)
            v += rj[ql + 4 * i];
        v += __shfl_xor_sync(0xFFFFFFFFu, v, 1);
        v += __shfl_xor_sync(0xFFFFFFFFu, v, 2);
        if (ql == 0) {
            const int gc = CAP_BATCH * (NBATCH - 1) + ecap;
            const int gr = img0 + eimg;
            float sc = v * inv[eimg];
            g_scores[(size_t)gr * C_N + gc] = sc;
            if (gr == gc) g_diag[gc] = sc;
        }
    }
}

// ---------------- loss epilogue ----------------
extern "C" __global__ void row_kernel()
{
    const int b = blockIdx.x;
    const int tid = threadIdx.x;
    const float di = g_diag[b];
    float local = 0.0f;
    for (int c = tid; c < C_N; c += blockDim.x) {
        if (c == b) continue;
        float sc = g_scores[(size_t)b * C_N + c];
        local += fmaxf(0.0f, MARGIN + sc - di)
               + fmaxf(0.0f, MARGIN + sc - g_diag[c]);
    }
    __shared__ float buf[128];
    buf[tid] = local;
    __syncthreads();
    for (int s = 64; s > 0; s >>= 1) {
        if (tid < s) buf[tid] += buf[tid + s];
        __syncthreads();
    }
    if (tid == 0) g_partial[b] = buf[0];
}

extern "C" __global__ void final_kernel(float* out)
{
    const int tid = threadIdx.x;
    float local = 0.0f;
    for (int i = tid; i < I_N; i += 256) local += g_partial[i];
    __shared__ float buf[256];
    buf[tid] = local;
    __syncthreads();
    for (int s = 128; s > 0; s >>= 1) {
        if (tid < s) buf[tid] += buf[tid + s];
        __syncthreads();
    }
    if (tid == 0) out[0] = buf[0] * (1.0f / ((float)I_N * (float)C_N));
}

// ---------------- launch ----------------
extern "C" void kernel_launch(void* const* d_in, const int* in_sizes, int n_in,
                              void* d_out, int out_size)
{
    const float* im   = (const float*)d_in[0];
    const float* s    = (const float*)d_in[1];
    const int*   im_l = (const int*)d_in[2];
    const int*   s_l  = (const int*)d_in[3];

    cudaFuncSetAttribute(xattn_kernel,
                         cudaFuncAttributeMaxDynamicSharedMemorySize, SMEM_BYTES);

    conv_kernel<<<(NA4 + NB4 + 255) / 256, 256>>>(im, s, s_l);
    xattn_kernel<<<NCTA, THREADS, SMEM_BYTES>>>(im_l, s_l);
    row_kernel<<<I_N, 128>>>();
    final_kernel<<<1, 256>>>((float*)d_out);
}

// round 16
// speedup vs baseline: 1.2198x; 1.0140x over previous
#include <cuda_runtime.h>
#include <cuda_fp16.h>
#include <stdint.h>

// ---------------- problem constants ----------------
#define I_N 1024
#define O_N 36
#define C_N 1024
#define W_N 60
#define D_N 64
#define MARGIN 0.2f

#define IMG_PER_CTA 7
#define NCTA 147            // ceil(1024/7)
#define THREADS 512         // 16 warps; warp w owns m16-tile w (256 rows total)
#define CAP_BATCH 8         // captions per B buffer (8KB each, fp16)
#define NBATCH (C_N / CAP_BATCH)

// ---------------- smem layout (bytes from 1024-aligned base) ----------------
#define OFF_A    0          // 256 rows x 128B (fp16)            = 32768
#define OFF_B    32768      // 2 bufs x 64KB (8 captions each)   = 131072
#define OFF_RMAX 163840     // 2 bufs x 8 x 256 floats           = 16384
#define OFF_INV  180224     // 7 floats
#define SMEM_BYTES (180256 + 1024)

// ---------------- device globals ----------------
__device__ __half gA [(size_t)I_N * O_N * D_N];
__device__ __half gBh[(size_t)C_N * 64 * D_N];   // words padded to 64 w/ duplicate of last valid word
__device__ float g_scores[(size_t)I_N * C_N];
__device__ float g_diag[I_N];
__device__ float g_partial[I_N];

// ---------------- helpers ----------------
__device__ __forceinline__ uint32_t smem_u32(const void* p) {
    uint32_t a;
    asm("{ .reg .u64 t; cvta.to.shared.u64 t, %1; cvt.u32.u64 %0, t; }" : "=r"(a) : "l"(p));
    return a;
}
#define SW128(off) ((off) ^ (((off) >> 3) & 0x70))

__device__ __forceinline__ void ldsm4(uint32_t* r, uint32_t addr) {
    asm volatile("ldmatrix.sync.aligned.m8n8.x4.shared.b16 {%0,%1,%2,%3}, [%4];"
                 : "=r"(r[0]), "=r"(r[1]), "=r"(r[2]), "=r"(r[3]) : "r"(addr));
}
// fp16 inputs, fp16 accumulate: D/C are 2 packed f16x2 regs.
__device__ __forceinline__ void mma16816h(uint32_t* d, const uint32_t* a, const uint32_t* b) {
    asm volatile(
        "mma.sync.aligned.m16n8k16.row.col.f16.f16.f16.f16 "
        "{%0,%1}, {%2,%3,%4,%5}, {%6,%7}, {%0,%1};"
        : "+r"(d[0]), "+r"(d[1])
        : "r"(a[0]), "r"(a[1]), "r"(a[2]), "r"(a[3]), "r"(b[0]), "r"(b[1]));
}
__device__ __forceinline__ uint32_t hmax2u(uint32_t x, uint32_t y) {
    __half2 r = __hmax2(*reinterpret_cast<const __half2*>(&x),
                        *reinterpret_cast<const __half2*>(&y));
    return *reinterpret_cast<const uint32_t*>(&r);
}
#define CP16(dst, src) \
    asm volatile("cp.async.cg.shared.global [%0], [%1], 16;" :: "r"(dst), "l"(src))
#define CP_COMMIT()  asm volatile("cp.async.commit_group;" ::: "memory")
#define CP_WAIT(n)   asm volatile("cp.async.wait_group %0;" :: "n"(n) : "memory")

// ---------------- vectorized precompute: A + B convert/pad, 4 elems/thread ----
#define NA (I_N * O_N * D_N)
#define NB (C_N * 64 * D_N)
#define NA4 (NA / 4)
#define NB4 (NB / 4)

__device__ __forceinline__ uint2 cvt4(float4 v) {
    __half2 p0 = __floats2half2_rn(v.x, v.y);
    __half2 p1 = __floats2half2_rn(v.z, v.w);
    uint2 o;
    o.x = *reinterpret_cast<const uint32_t*>(&p0);
    o.y = *reinterpret_cast<const uint32_t*>(&p1);
    return o;
}

extern "C" __global__ void conv_kernel(const float* __restrict__ im,
                                       const float* __restrict__ s,
                                       const int* __restrict__ s_l)
{
    int idx = blockIdx.x * blockDim.x + threadIdx.x;
    if (idx < NA4) {
        float4 v = reinterpret_cast<const float4*>(im)[idx];
        reinterpret_cast<uint2*>(gA)[idx] = cvt4(v);
    } else if (idx < NA4 + NB4) {
        int g = idx - NA4;
        int d4 = g & 15;                 // 4-elem group within d (0..15)
        int w  = (g >> 4) & 63;          // padded word column
        int c  = g >> 10;                // caption
        int clen = s_l[c];
        // Pad words [clen, 64) with a COPY of word clen-1: max over any computed
        // superset of columns equals the true max -> no masking downstream.
        int ws = (w < clen) ? w : (clen - 1);
        float4 v = reinterpret_cast<const float4*>(
                       s + ((size_t)c * W_N + ws) * D_N)[d4];
        reinterpret_cast<uint2*>(gBh)[(c << 10) + (w << 4) + d4] = cvt4(v);
    }
}

// ---------------- main xattn-scores kernel ----------------
extern "C" __global__ void __launch_bounds__(THREADS, 1)
xattn_kernel(const int* __restrict__ im_l, const int* __restrict__ s_l)
{
    extern __shared__ char smraw[];
    const uint32_t raw_u = smem_u32(smraw);
    const uint32_t abase = (raw_u + 1023u) & ~1023u;
    char* base = smraw + (abase - raw_u);

    const int tid  = threadIdx.x;
    const int wid  = tid >> 5;          // 0..15, owns m16-tile wid
    const int lane = tid & 31;
    const int img0 = blockIdx.x * IMG_PER_CTA;
    const int n_img = (I_N - img0 < IMG_PER_CTA) ? (I_N - img0) : IMG_PER_CTA;

    float* rmaxb = (float*)(base + OFF_RMAX);  // [2][8][256]
    float* inv   = (float*)(base + OFF_INV);
    if (tid < n_img)
        inv[tid] = 1.0f / ((float)im_l[img0 + tid] + 1e-6f);

    // ---- stage A into swizzled smem; zero-pad rows >= n_img*36 ----
    {
        const int vchunks = n_img * O_N * 8;
        const uint4* ga = (const uint4*)(gA + (size_t)img0 * O_N * D_N);
        const uint4 z = make_uint4(0, 0, 0, 0);
        #pragma unroll
        for (int t = tid; t < 2048; t += THREADS) {
            uint32_t off = SW128((uint32_t)(t * 16));
            *(uint4*)(base + OFF_A + off) = (t < vchunks) ? ga[t] : z;
        }
    }

    // ---- prefetch B batch 0 (captions 0..7): 64 KB ----
    {
        const char* sh = (const char*)(gBh);
        uint32_t dst = abase + OFF_B;
        #pragma unroll
        for (int t = tid; t < 4096; t += THREADS) {
            uint32_t off = SW128((uint32_t)(t * 16));
            CP16(dst + off, sh + t * 16);
        }
    }
    CP_COMMIT();

    // ---- ldmatrix addressing invariants ----
    const uint32_t xr    = (uint32_t)((lane & 7) << 4);
    const uint32_t aColB = (uint32_t)((lane >> 4) << 4);
    const uint32_t aRow  = (uint32_t)(wid * 16 + (lane & 15));
    // B ldsm4: lane L -> row (L&7), matrix (L>>3); one x4 covers 2 k-steps.
    const uint32_t bRowOff = (uint32_t)((lane & 7) * 128);
    const uint32_t bMat    = (uint32_t)((lane >> 3) << 4);

    // epilogue mapping: quad q (0..55) -> (image q>>3, caption q&7)
    const int quad = tid >> 2;
    const int ql   = tid & 3;
    const int eimg = quad >> 3;
    const int ecap = quad & 7;
    const bool edo = (quad < 56) && (eimg < n_img);

    __syncthreads();   // A staged (needed before ldsm of A)

    // ---- A fragments resident in registers (one m-tile per warp) ----
    uint32_t af[4][4];
    #pragma unroll
    for (int k = 0; k < 4; ++k)
        ldsm4(af[k], abase + OFF_A + aRow * 128 + ((aColB + (uint32_t)(k * 32)) ^ xr));

    const uint32_t NEGINF2 = 0xFC00FC00u;   // packed {-inf, -inf} fp16

    for (int cc = 0; cc < NBATCH; ++cc) {
        // prefetch next batch (64 KB)
        if (cc + 1 < NBATCH) {
            const char* sh = (const char*)(gBh + (size_t)(cc + 1) * 32768);
            uint32_t dst = abase + OFF_B + (uint32_t)((cc + 1) & 1) * 65536;
            #pragma unroll
            for (int t = tid; t < 4096; t += THREADS) {
                uint32_t off = SW128((uint32_t)(t * 16));
                CP16(dst + off, sh + t * 16);
            }
            CP_COMMIT();
            CP_WAIT(1);
        } else {
            CP_WAIT(0);
        }
        // ONE barrier per batch: orders (a) B(cc) visibility for all warps,
        // (b) completeness of rmax(cc-1) writes, (c) WAR on rmax(cc) buffer.
        __syncthreads();

        // ---- deferred score epilogue for batch cc-1 (reads buf (cc-1)&1) ----
        if (cc > 0 && edo) {
            const float* rj = rmaxb + (uint32_t)((cc - 1) & 1) * 2048
                             + ecap * 256 + eimg * O_N;
            float v = 0.0f;
            #pragma unroll
            for (int i = 0; i < 9; ++i)
                v += rj[ql + 4 * i];
            v += __shfl_xor_sync(0xFFFFFFFFu, v, 1);
            v += __shfl_xor_sync(0xFFFFFFFFu, v, 2);
            if (ql == 0) {
                const int gc = CAP_BATCH * (cc - 1) + ecap;
                const int gr = img0 + eimg;
                float sc = v * inv[eimg];
                g_scores[(size_t)gr * C_N + gc] = sc;
                if (gr == gc) g_diag[gc] = sc;   // fused diag extraction
            }
        }

        // batch caption lengths: 2 vector LDGs (s_l offset is 32B-aligned)
        const int4 cl0 = *(const int4*)(s_l + CAP_BATCH * cc);
        const int4 cl1 = *(const int4*)(s_l + CAP_BATCH * cc + 4);
        const int clens[8] = { cl0.x, cl0.y, cl0.z, cl0.w,
                               cl1.x, cl1.y, cl1.z, cl1.w };

        float* rmax = rmaxb + (uint32_t)(cc & 1) * 2048;   // write buf cc&1

        #pragma unroll
        for (int j = 0; j < CAP_BATCH; ++j) {
            const int nlim = (clens[j] + 7) >> 3;  // n8 tiles to compute
            const uint32_t bh_base = abase + OFF_B + (uint32_t)((cc & 1) << 16)
                                    + (uint32_t)(j << 13);

            // packed column-pair maxes: mxp[0] = row r, mxp[1] = row r+8
            uint32_t mxp[2] = { NEGINF2, NEGINF2 };

            #pragma unroll
            for (int p = 0; p < 4; ++p) {
                const int n0 = 2 * p;
                if (n0 < nlim) {
                    const bool has2 = (n0 + 1) < nlim;
                    // bf[kp][0..3]: {r0,r1}=k-step 2kp, {r2,r3}=k-step 2kp+1
                    uint32_t bf0[2][4], bf1[2][4];
                    #pragma unroll
                    for (int kp = 0; kp < 2; ++kp)
                        ldsm4(bf0[kp], bh_base + (uint32_t)(n0 * 1024) + bRowOff
                                      + (((uint32_t)(kp * 64) + bMat) ^ xr));
                    if (has2) {
                        #pragma unroll
                        for (int kp = 0; kp < 2; ++kp)
                            ldsm4(bf1[kp], bh_base + (uint32_t)((n0 + 1) * 1024) + bRowOff
                                          + (((uint32_t)(kp * 64) + bMat) ^ xr));
                    }

                    uint32_t acc0[2] = { 0u, 0u };
                    uint32_t acc1[2] = { 0u, 0u };

                    #pragma unroll
                    for (int k = 0; k < 4; ++k) {
                        mma16816h(acc0, af[k], &bf0[k >> 1][(k & 1) * 2]);
                        if (has2)
                            mma16816h(acc1, af[k], &bf1[k >> 1][(k & 1) * 2]);
                    }

                    mxp[0] = hmax2u(mxp[0], acc0[0]);
                    mxp[1] = hmax2u(mxp[1], acc0[1]);
                    if (has2) {
                        mxp[0] = hmax2u(mxp[0], acc1[0]);
                        mxp[1] = hmax2u(mxp[1], acc1[1]);
                    }
                }
            }

            // unpack packed maxes -> float, fold halves, quad reduce
            float mx[2];
            {
                __half2 h0 = *reinterpret_cast<const __half2*>(&mxp[0]);
                __half2 h1 = *reinterpret_cast<const __half2*>(&mxp[1]);
                mx[0] = fmaxf(__low2float(h0), __high2float(h0));
                mx[1] = fmaxf(__low2float(h1), __high2float(h1));
            }
            #pragma unroll
            for (int q = 0; q < 2; ++q) {
                mx[q] = fmaxf(mx[q], __shfl_xor_sync(0xFFFFFFFFu, mx[q], 1));
                mx[q] = fmaxf(mx[q], __shfl_xor_sync(0xFFFFFFFFu, mx[q], 2));
            }
            if ((lane & 3) == 0) {
                float* rj = rmax + j * 256;
                const int row0 = wid * 16 + (lane >> 2);
                rj[row0]     = mx[0];
                rj[row0 + 8] = mx[1];
            }
        }
    }

    // ---- final batch's epilogue ----
    __syncthreads();
    if (edo) {
        const float* rj = rmaxb + (uint32_t)((NBATCH - 1) & 1) * 2048
                         + ecap * 256 + eimg * O_N;
        float v = 0.0f;
        #pragma unroll
        for (int i = 0; i < 9; ++i)
            v += rj[ql + 4 * i];
        v += __shfl_xor_sync(0xFFFFFFFFu, v, 1);
        v += __shfl_xor_sync(0xFFFFFFFFu, v, 2);
        if (ql == 0) {
            const int gc = CAP_BATCH * (NBATCH - 1) + ecap;
            const int gr = img0 + eimg;
            float sc = v * inv[eimg];
            g_scores[(size_t)gr * C_N + gc] = sc;
            if (gr == gc) g_diag[gc] = sc;
        }
    }
}

// ---------------- loss epilogue ----------------
extern "C" __global__ void row_kernel()
{
    const int b = blockIdx.x;
    const int tid = threadIdx.x;
    const float di = g_diag[b];
    float local = 0.0f;
    for (int c = tid; c < C_N; c += blockDim.x) {
        if (c == b) continue;
        float sc = g_scores[(size_t)b * C_N + c];
        local += fmaxf(0.0f, MARGIN + sc - di)
               + fmaxf(0.0f, MARGIN + sc - g_diag[c]);
    }
    __shared__ float buf[128];
    buf[tid] = local;
    __syncthreads();
    for (int s = 64; s > 0; s >>= 1) {
        if (tid < s) buf[tid] += buf[tid + s];
        __syncthreads();
    }
    if (tid == 0) g_partial[b] = buf[0];
}

extern "C" __global__ void final_kernel(float* out)
{
    const int tid = threadIdx.x;
    float local = 0.0f;
    for (int i = tid; i < I_N; i += 256) local += g_partial[i];
    __shared__ float buf[256];
    buf[tid] = local;
    __syncthreads();
    for (int s = 128; s > 0; s >>= 1) {
        if (tid < s) buf[tid] += buf[tid + s];
        __syncthreads();
    }
    if (tid == 0) out[0] = buf[0] * (1.0f / ((float)I_N * (float)C_N));
}

// ---------------- launch ----------------
extern "C" void kernel_launch(void* const* d_in, const int* in_sizes, int n_in,
                              void* d_out, int out_size)
{
    const float* im   = (const float*)d_in[0];
    const float* s    = (const float*)d_in[1];
    const int*   im_l = (const int*)d_in[2];
    const int*   s_l  = (const int*)d_in[3];

    cudaFuncSetAttribute(xattn_kernel,
                         cudaFuncAttributeMaxDynamicSharedMemorySize, SMEM_BYTES);

    conv_kernel<<<(NA4 + NB4 + 255) / 256, 256>>>(im, s, s_l);
    xattn_kernel<<<NCTA, THREADS, SMEM_BYTES>>>(im_l, s_l);
    row_kernel<<<I_N, 128>>>();
    final_kernel<<<1, 256>>>((float*)d_out);
}